// round 15
// baseline (speedup 1.0000x reference)
#include <cuda_runtime.h>
#include <cstdint>
#include <cstddef>

// SNN Leaky scan. reset_t = H(mem_{t-1}-1); mem_t = beta*mem_{t-1}+x_t-reset_t; spk_t = H(mem_t-1)
//
// Recurrence (bit-identical to reference; rel_err 0 verified R11/R13):
//   a_t   = __fmaf_rn(beta, mem_{t-1}, x_t);   mem_t = a_t - rf_{t-1}   (exact, Sterbenz)
//   m1 = sgn(1 - a_t), m2 = sgn(2 - a_t)       (off the carried cycle)
//   mask_t = m2&mask_{t-1} | m1&~mask_{t-1}    (single LOP3 carried dep)
//   rf_t   = float_bits(mask_t & 0x3F800000)   ({0.0f,1.0f}; no predicates)
//
// KEY CHANGE vs R13 (best, 63.5us): ILP-2 in the compute warp. 128 CTAs x 64 rows;
// each compute lane interleaves TWO independent rows (lane, lane+32), so two chains
// share one chain-latency window (period/step-pair ~= max(chain, issue) instead of
// 2x chain). R5's ILP-2 regression had a confounded single-io-warp config; here the
// R13-proven io specialization is kept and scaled:
//   warp 0: compute (2 rows/lane)   warp 1: loader (cp.async, 2 chunks ahead)
//   warp 2: storer rows 0-31        warp 3: storer rows 32-63
// Grid 128 (all wave-1 resident; wall = per-CTA phase span). 3-in/2-out SMEM ring,
// odd row stride (33 f4) -> conflict-free LDS/STS.128.

namespace {
constexpr int N_TOTAL  = 8192;
constexpr int T_STEPS  = 4000;
constexpr float BETA   = 0.95f;

constexpr int ROWS     = 64;     // rows per CTA (2 per compute lane)
constexpr int THREADS  = 128;    // compute, loader, storerA, storerB
constexpr int TCHUNK   = 128;    // time steps per chunk
constexpr int TC4      = TCHUNK / 4;                          // 32 float4 per row-chunk
constexpr int NCHUNK   = (T_STEPS + TCHUNK - 1) / TCHUNK;     // 32 (31 full + 32-step tail)
constexpr int TAIL4    = (T_STEPS - (NCHUNK - 1) * TCHUNK) / 4;  // 8
constexpr int RSTRIDE  = TC4 + 1;                             // 33: odd stride, conflict-free
constexpr int BUFELEM  = ROWS * RSTRIDE;                      // float4 per buffer
constexpr size_t SMEM_BYTES = (size_t)(3 + 2) * BUFELEM * sizeof(float4);  // 169 KB
}

__device__ __forceinline__ void cp_async16(void* sdst, const void* gsrc) {
    uint32_t s = (uint32_t)__cvta_generic_to_shared(sdst);
    asm volatile("cp.async.cg.shared.global [%0], [%1], 16;" :: "r"(s), "l"(gsrc));
}
__device__ __forceinline__ void cp_commit() {
    asm volatile("cp.async.commit_group;" ::: "memory");
}
template <int NN>
__device__ __forceinline__ void cp_wait() {
    asm volatile("cp.async.wait_group %0;" :: "n"(NN) : "memory");
}

__device__ __forceinline__ uint32_t sgnmask(float v) {
    return (uint32_t)(__float_as_int(v) >> 31);
}
__device__ __forceinline__ uint32_t lop3_sel(uint32_t a, uint32_t b, uint32_t c) {
    uint32_t r;
    asm("lop3.b32 %0, %1, %2, %3, 0xD8;" : "=r"(r) : "r"(a), "r"(b), "r"(c));
    return r;
}

struct SnnState {
    float mem;
    float rf;
    uint32_t mask;
};

__device__ __forceinline__ float snn_step(SnnState& s, float x) {
    float a = __fmaf_rn(BETA, s.mem, x);
    s.mem = a - s.rf;                      // exact (Sterbenz)
    uint32_t m1 = sgnmask(1.0f - a);
    uint32_t m2 = sgnmask(2.0f - a);
    s.mask = lop3_sel(m1, m2, s.mask);
    s.rf = __uint_as_float(s.mask & 0x3F800000u);
    return s.rf;
}

// interleave two independent chains step-by-step
__device__ __forceinline__ void snn_step4x2(SnnState& sa, SnnState& sb,
                                            float4 xa, float4 xb,
                                            float4& oa, float4& ob) {
    oa.x = snn_step(sa, xa.x);  ob.x = snn_step(sb, xb.x);
    oa.y = snn_step(sa, xa.y);  ob.y = snn_step(sb, xb.y);
    oa.z = snn_step(sa, xa.z);  ob.z = snn_step(sb, xb.z);
    oa.w = snn_step(sa, xa.w);  ob.w = snn_step(sb, xb.w);
}

__global__ void __launch_bounds__(THREADS, 1)
snn_leaky_ws_kernel(const float* __restrict__ inp, float* __restrict__ out) {
    extern __shared__ float4 smem[];
    const int tid  = threadIdx.x;
    const int lane = tid & 31;
    const int wid  = tid >> 5;            // 0 compute, 1 loader, 2 storerA, 3 storerB
    const int rowBase = blockIdx.x * ROWS;

    float4* inbuf[3]  = { smem, smem + BUFELEM, smem + 2 * BUFELEM };
    float4* outbuf[2] = { smem + 3 * BUFELEM, smem + 4 * BUFELEM };

    // ---- prologue: loader preloads chunks 0 and 1 (one commit group each) ----
    if (wid == 1) {
        #pragma unroll
        for (int c0 = 0; c0 < 2; ++c0) {
            #pragma unroll 8
            for (int r = 0; r < ROWS; ++r) {
                const float4* g = reinterpret_cast<const float4*>(
                    inp + (size_t)(rowBase + r) * T_STEPS + c0 * TCHUNK);
                cp_async16(&inbuf[c0][r * RSTRIDE + lane], g + lane);
            }
            cp_commit();
        }
    }

    SnnState stA, stB;
    stA.mem = 0.0f; stA.rf = 0.0f; stA.mask = 0u;
    stB.mem = 0.0f; stB.rf = 0.0f; stB.mask = 0u;

    for (int c = 0; c <= NCHUNK; ++c) {
        if (wid == 1) cp_wait<1>();   // input chunk c landed (<=1 group outstanding)
        __syncthreads();

        if (wid == 0) {
            // ---- compute chunk c: rows (lane) and (lane+32) interleaved ----
            if (c < NCHUNK) {
                const float4* __restrict__ rinA  = inbuf[c % 3] + lane * RSTRIDE;
                const float4* __restrict__ rinB  = rinA + 32 * RSTRIDE;
                float4* __restrict__       routA = outbuf[c & 1] + lane * RSTRIDE;
                float4* __restrict__       routB = routA + 32 * RSTRIDE;
                const int nv4 = (c == NCHUNK - 1) ? TAIL4 : TC4;
                // software pipeline: LDS issued 1 f4-iter ahead (two rows per iter)
                float4 xa0 = rinA[0], xb0 = rinB[0];
                #pragma unroll
                for (int t4 = 0; t4 < TC4; ++t4) {
                    if (t4 >= nv4) break;
                    float4 xa1, xb1;
                    if (t4 + 1 < nv4) { xa1 = rinA[t4 + 1]; xb1 = rinB[t4 + 1]; }
                    float4 oa, ob;
                    snn_step4x2(stA, stB, xa0, xb0, oa, ob);
                    routA[t4] = oa;
                    routB[t4] = ob;
                    xa0 = xa1; xb0 = xb1;
                }
            }
        } else if (wid >= 2) {
            // ---- storers: spikes of chunk c-1 (coalesced float4 STG) ----
            if (c >= 1) {
                const int cp = c - 1;
                const int nv4 = (cp == NCHUNK - 1) ? TAIL4 : TC4;
                const int r0 = (wid - 2) * 32;        // 0 or 32
                const float4* b = outbuf[cp & 1];
                if (lane < nv4) {
                    #pragma unroll 8
                    for (int r = r0; r < r0 + 32; ++r) {
                        float4 v = b[r * RSTRIDE + lane];
                        reinterpret_cast<float4*>(
                            out + (size_t)(rowBase + r) * T_STEPS + cp * TCHUNK)[lane] = v;
                    }
                }
            }
        } else {
            // ---- loader: prefetch input chunk c+2 ----
            if (c + 2 < NCHUNK) {
                const int cn = c + 2;
                const int nvn = (cn == NCHUNK - 1) ? TAIL4 : TC4;
                float4* b = inbuf[cn % 3];
                if (lane < nvn) {
                    #pragma unroll 8
                    for (int r = 0; r < ROWS; ++r) {
                        const float4* g = reinterpret_cast<const float4*>(
                            inp + (size_t)(rowBase + r) * T_STEPS + cn * TCHUNK);
                        cp_async16(&b[r * RSTRIDE + lane], g + lane);
                    }
                }
            }
            cp_commit();   // loader only: uniform group counting
        }
    }
}

extern "C" void kernel_launch(void* const* d_in, const int* in_sizes, int n_in,
                              void* d_out, int out_size) {
    (void)in_sizes; (void)n_in; (void)out_size;
    const float* inp = (const float*)d_in[0];
    float* out = (float*)d_out;

    cudaFuncSetAttribute(snn_leaky_ws_kernel,
                         cudaFuncAttributeMaxDynamicSharedMemorySize,
                         (int)SMEM_BYTES);
    snn_leaky_ws_kernel<<<N_TOTAL / ROWS, THREADS, SMEM_BYTES>>>(inp, out);
}

// round 16
// speedup vs baseline: 1.6208x; 1.6208x over previous
#include <cuda_runtime.h>
#include <cstdint>
#include <cstddef>

// SNN Leaky scan. reset_t = H(mem_{t-1}-1); mem_t = beta*mem_{t-1}+x_t-reset_t; spk_t = H(mem_t-1)
//
// Recurrence (bit-identical to reference; rel_err 0 verified R11/R13):
//   a_t   = __fmaf_rn(beta, mem_{t-1}, x_t);   mem_t = a_t - rf_{t-1}   (exact, Sterbenz)
//   m1 = sgn(1 - a_t), m2 = sgn(2 - a_t)       (off the carried cycle)
//   mask_t = m2&mask_{t-1} | m1&~mask_{t-1}    (single LOP3 carried dep)
//   rf_t   = float_bits(mask_t & 0x3F800000)   ({0.0f,1.0f}; no predicates)
//
// KEY CHANGE vs R13 (best, 63.5us): SMSP de-collision. warp->SMSP is wid%4, and
// co-resident CTAs are (bid, bid+148) [classic LUT, all wave-1 at 256 CTAs], so in
// R13 BOTH compute warps of a 2-CTA SM sat on SMSP 0 sharing one fma pipe
// (4 fma-ops/step x rt2 x 2 warps = 16 cyc/step — the measured wall).
// Fix: 4 warps with roles rotated by 2 for bid>=148:
//   role = (wid + (bid>=148 ? 2 : 0)) & 3
//   0=compute (1 row/lane)  1=loader (cp.async 2 ahead)  2=storer rows 0-15  3=storer rows 16-31
// => compute warps land on SMSP 0 AND 2, each alone on its fma pipe (8 cyc/step floor).
// Everything else frozen from R13: 256 CTAs x 32 rows, TCHUNK=128 (TC4=32),
// 3-in/2-out SMEM ring, odd row stride (33 f4) -> conflict-free LDS/STS.128.

namespace {
constexpr int N_TOTAL  = 8192;
constexpr int T_STEPS  = 4000;
constexpr float BETA   = 0.95f;

constexpr int ROWS     = 32;     // rows per CTA (1 per compute lane)
constexpr int THREADS  = 128;    // 4 warps: compute / loader / storerA / storerB
constexpr int TCHUNK   = 128;    // time steps per chunk
constexpr int TC4      = TCHUNK / 4;                          // 32 float4 per row-chunk
constexpr int NCHUNK   = (T_STEPS + TCHUNK - 1) / TCHUNK;     // 32 (31 full + 32-step tail)
constexpr int TAIL4    = (T_STEPS - (NCHUNK - 1) * TCHUNK) / 4;  // 8
constexpr int RSTRIDE  = TC4 + 1;                             // 33: odd stride, conflict-free
constexpr int BUFELEM  = ROWS * RSTRIDE;                      // float4 per buffer
constexpr size_t SMEM_BYTES = (size_t)(3 + 2) * BUFELEM * sizeof(float4);  // 84.5 KB
}

__device__ __forceinline__ void cp_async16(void* sdst, const void* gsrc) {
    uint32_t s = (uint32_t)__cvta_generic_to_shared(sdst);
    asm volatile("cp.async.cg.shared.global [%0], [%1], 16;" :: "r"(s), "l"(gsrc));
}
__device__ __forceinline__ void cp_commit() {
    asm volatile("cp.async.commit_group;" ::: "memory");
}
template <int NN>
__device__ __forceinline__ void cp_wait() {
    asm volatile("cp.async.wait_group %0;" :: "n"(NN) : "memory");
}

__device__ __forceinline__ uint32_t sgnmask(float v) {
    return (uint32_t)(__float_as_int(v) >> 31);
}
__device__ __forceinline__ uint32_t lop3_sel(uint32_t a, uint32_t b, uint32_t c) {
    uint32_t r;
    asm("lop3.b32 %0, %1, %2, %3, 0xD8;" : "=r"(r) : "r"(a), "r"(b), "r"(c));
    return r;
}

struct SnnState {
    float mem;      // mem_{t-1}  (bit-identical to reference recurrence)
    float rf;       // r_{t-1} as float in {0.0f, 1.0f}
    uint32_t mask;  // splat of spk_{t-1}
};

__device__ __forceinline__ float snn_step(SnnState& s, float x) {
    float a = __fmaf_rn(BETA, s.mem, x);
    s.mem = a - s.rf;                      // exact (Sterbenz)
    uint32_t m1 = sgnmask(1.0f - a);       // [a > 1]
    uint32_t m2 = sgnmask(2.0f - a);       // [a > 2]
    s.mask = lop3_sel(m1, m2, s.mask);     // spk_t splat
    s.rf = __uint_as_float(s.mask & 0x3F800000u);
    return s.rf;
}

__device__ __forceinline__ float4 snn_step4(SnnState& s, float4 x) {
    float4 o;
    o.x = snn_step(s, x.x);
    o.y = snn_step(s, x.y);
    o.z = snn_step(s, x.z);
    o.w = snn_step(s, x.w);
    return o;
}

__global__ void __launch_bounds__(THREADS, 2)
snn_leaky_ws_kernel(const float* __restrict__ inp, float* __restrict__ out) {
    extern __shared__ float4 smem[];
    const int tid  = threadIdx.x;
    const int lane = tid & 31;
    const int wid  = tid >> 5;
    // role rotation: co-resident CTAs (bid, bid+148) get compute on SMSP 0 vs 2
    const int role = (wid + ((blockIdx.x >= 148) ? 2 : 0)) & 3;
    const int rowBase = blockIdx.x * ROWS;

    float4* inbuf[3]  = { smem, smem + BUFELEM, smem + 2 * BUFELEM };
    float4* outbuf[2] = { smem + 3 * BUFELEM, smem + 4 * BUFELEM };

    // ---- prologue: loader preloads chunks 0 and 1 (one commit group each) ----
    if (role == 1) {
        #pragma unroll
        for (int c0 = 0; c0 < 2; ++c0) {
            #pragma unroll 8
            for (int r = 0; r < ROWS; ++r) {
                const float4* g = reinterpret_cast<const float4*>(
                    inp + (size_t)(rowBase + r) * T_STEPS + c0 * TCHUNK);
                cp_async16(&inbuf[c0][r * RSTRIDE + lane], g + lane);
            }
            cp_commit();
        }
    }

    SnnState st;
    st.mem = 0.0f; st.rf = 0.0f; st.mask = 0u;

    for (int c = 0; c <= NCHUNK; ++c) {
        if (role == 1) cp_wait<1>();   // input chunk c landed (<=1 group outstanding)
        __syncthreads();

        if (role == 0) {
            // ---- compute chunk c: 1 row per lane, spikes -> outbuf ----
            if (c < NCHUNK) {
                const float4* __restrict__ rin  = inbuf[c % 3] + lane * RSTRIDE;
                float4* __restrict__       rout = outbuf[c & 1] + lane * RSTRIDE;
                if (c != NCHUNK - 1) {
                    float4 xa = rin[0];            // LDS pipelined 2 iters ahead
                    float4 xb = rin[1];
                    #pragma unroll
                    for (int t4 = 0; t4 < TC4; ++t4) {
                        float4 xc;
                        if (t4 + 2 < TC4) xc = rin[(t4 + 2)];
                        rout[t4] = snn_step4(st, xa);
                        xa = xb; xb = xc;
                    }
                } else {
                    float4 xa = rin[0];
                    float4 xb = rin[1];
                    #pragma unroll
                    for (int t4 = 0; t4 < TAIL4; ++t4) {
                        float4 xc;
                        if (t4 + 2 < TAIL4) xc = rin[(t4 + 2)];
                        rout[t4] = snn_step4(st, xa);
                        xa = xb; xb = xc;
                    }
                }
            }
        } else if (role >= 2) {
            // ---- storers: spikes of chunk c-1, 16 rows each (coalesced STG.128) ----
            if (c >= 1) {
                const int cp = c - 1;
                const int nv4 = (cp == NCHUNK - 1) ? TAIL4 : TC4;
                const int r0 = (role - 2) * 16;       // 0 or 16
                const float4* b = outbuf[cp & 1];
                if (lane < nv4) {
                    #pragma unroll 4
                    for (int r = r0; r < r0 + 16; ++r) {
                        float4 v = b[r * RSTRIDE + lane];
                        reinterpret_cast<float4*>(
                            out + (size_t)(rowBase + r) * T_STEPS + cp * TCHUNK)[lane] = v;
                    }
                }
            }
        } else {
            // ---- loader: prefetch input chunk c+2 ----
            if (c + 2 < NCHUNK) {
                const int cn = c + 2;
                const int nvn = (cn == NCHUNK - 1) ? TAIL4 : TC4;
                float4* b = inbuf[cn % 3];
                if (lane < nvn) {
                    #pragma unroll 8
                    for (int r = 0; r < ROWS; ++r) {
                        const float4* g = reinterpret_cast<const float4*>(
                            inp + (size_t)(rowBase + r) * T_STEPS + cn * TCHUNK);
                        cp_async16(&b[r * RSTRIDE + lane], g + lane);
                    }
                }
            }
            cp_commit();   // loader only: uniform group counting
        }
    }
}

extern "C" void kernel_launch(void* const* d_in, const int* in_sizes, int n_in,
                              void* d_out, int out_size) {
    (void)in_sizes; (void)n_in; (void)out_size;
    const float* inp = (const float*)d_in[0];
    float* out = (float*)d_out;

    cudaFuncSetAttribute(snn_leaky_ws_kernel,
                         cudaFuncAttributeMaxDynamicSharedMemorySize,
                         (int)SMEM_BYTES);
    snn_leaky_ws_kernel<<<N_TOTAL / ROWS, THREADS, SMEM_BYTES>>>(inp, out);
}